// round 10
// baseline (speedup 1.0000x reference)
#include <cuda_runtime.h>
#include <cstdint>

// FeatureResidual: 1-NN over 8-dim keys in a 100000x40 table, then feature residual.
#define BATCH  1024
#define KDIM   8
#define FDIM   32
#define NROWS  100000
#define NCOLS  40

#define QGROUPS   2                 // query halves (512 queries each)
#define NSLICES   296               // grid = 296 x 2 = 592 blocks = 4/SM exact wave
#define TPB       128
#define QPT       4                 // queries per thread (128*4 = 512 per block)
#define ROWS_PER  338               // 296*338 >= 100000; last slice 290 (even)
#define MAXPAIRS  169
#define REC       20                // floats per pair record: 16 key + 2 nh + 2 pad
#define CH        32                // pairs per chunk (index granularity)

typedef unsigned long long u64;

// Per-query packed (enc(score) << 32 | ~row). Max = best score; ties -> lowest row.
// Zero-initialized at module load; finalizing block resets to 0 each launch.
__device__ u64 g_best[BATCH];
__device__ unsigned g_cnt[QGROUPS];   // zero-init; reset each launch

// ---------- f32x2 helpers ----------
__device__ __forceinline__ u64 pack2(float lo, float hi) {
    u64 r; asm("mov.b64 %0, {%1, %2};" : "=l"(r) : "f"(lo), "f"(hi)); return r;
}
__device__ __forceinline__ void unpack2(u64 p, float &lo, float &hi) {
    asm("mov.b64 {%0, %1}, %2;" : "=f"(lo), "=f"(hi) : "l"(p));
}
__device__ __forceinline__ u64 fma2(u64 a, u64 b, u64 c) {
    u64 d; asm("fma.rn.f32x2 %0, %1, %2, %3;" : "=l"(d) : "l"(a), "l"(b), "l"(c)); return d;
}
// Monotonic-increasing encode of float (u32 compare order == float order).
// Always > 0 for finite inputs, so g_best==0 is a safe atomicMax identity.
__device__ __forceinline__ unsigned enc_inc(float f) {
    int s = __float_as_int(f);
    return (s < 0) ? ~(unsigned)s : ((unsigned)s | 0x80000000u);
}

__global__ __launch_bounds__(TPB, 4)   // 128-reg budget; hot-loop live set ~100
void fused_kernel(const float* __restrict__ pk,
                  const float* __restrict__ feat,
                  const float* __restrict__ table,
                  const int*   __restrict__ kidx,
                  const int*   __restrict__ fidx,
                  float* __restrict__ out) {
    // Pair record p (80B, 16B-aligned): [k0e,k0o, ..., k7e,k7o, nh_e,nh_o, pad,pad]
    __shared__ __align__(16) float sRec[MAXPAIRS * REC];
    __shared__ int sKidx[KDIM];
    __shared__ int sF[FDIM];
    __shared__ unsigned sIsLast;

    const int t     = threadIdx.x;
    const int slice = blockIdx.x;
    const int grp   = blockIdx.y;

    if (t < KDIM) sKidx[t] = kidx[t];
    __syncthreads();

    const int rowBase = slice * ROWS_PER;
    const int nr      = min(ROWS_PER, NROWS - rowBase);   // even for this geometry
    const int npairs  = nr >> 1;
    const int nchunks = (npairs + CH - 1) / CH;

    // Stage keys interleaved by row pair (float2 fast path when key cols contiguous).
    bool kcontig = ((sKidx[0] & 1) == 0);
    #pragma unroll
    for (int i = 1; i < KDIM; i++) kcontig = kcontig && (sKidx[i] == sKidx[0] + i);
    if (kcontig) {
        const int c0 = sKidx[0];
        for (int e = t; e < nr * (KDIM / 2); e += TPB) {
            int r = e >> 2, c2 = e & 3;
            float2 v = *(const float2*)(table + (size_t)(rowBase + r) * NCOLS + c0 + 2 * c2);
            float* dst = sRec + (r >> 1) * REC + (r & 1);
            dst[4 * c2]     = v.x;
            dst[4 * c2 + 2] = v.y;
        }
    } else {
        for (int e = t; e < nr * KDIM; e += TPB) {
            int r = e >> 3, c = e & 7;
            float v = table[(size_t)(rowBase + r) * NCOLS + sKidx[c]];
            sRec[(r >> 1) * REC + (c << 1) + (r & 1)] = v;
        }
    }
    __syncthreads();
    // -0.5*||k||^2 per row, stored pair-adjacent at record offset 16.
    for (int r = t; r < nr; r += TPB) {
        const float* kr = sRec + (r >> 1) * REC + (r & 1);
        float s = kr[0] * kr[0];
        #pragma unroll
        for (int i = 1; i < KDIM; i++) s = fmaf(kr[2 * i], kr[2 * i], s);
        sRec[(r >> 1) * REC + 16 + (r & 1)] = -0.5f * s;
    }

    // Prologue: 4 queries per thread, duplicate-packed (64 regs).
    const int qbase = grp * (TPB * QPT);
    u64 q[QPT][KDIM];
    #pragma unroll
    for (int j = 0; j < QPT; j++) {
        const float4* pq = (const float4*)(pk + (size_t)(qbase + t + TPB * j) * KDIM);
        float4 a0 = pq[0], a1 = pq[1];
        float a[KDIM] = {a0.x, a0.y, a0.z, a0.w, a1.x, a1.y, a1.z, a1.w};
        #pragma unroll
        for (int i = 0; i < KDIM; i++) q[j][i] = pack2(a[i], a[i]);
    }

    float bsE[QPT], bsO[QPT];   // running maxima over even / odd rows
    int   bc[QPT];              // chunk index holding the best
    #pragma unroll
    for (int j = 0; j < QPT; j++) {
        bsE[j] = -__int_as_float(0x7f800000);
        bsO[j] = -__int_as_float(0x7f800000);
        bc[j]  = 0;
    }

    __syncthreads();

    // Hot loop: per pair, 5 LDS + per query 8 FFMA2 + 2 FMNMX. No index tracking,
    // no predicates — chunk id recorded once per CH pairs, row rescanned at end.
    for (int c = 0; c < nchunks; c++) {
        const int p0 = c * CH;
        const int p1 = min(p0 + CH, npairs);

        float pb[QPT];
        #pragma unroll
        for (int j = 0; j < QPT; j++) pb[j] = fmaxf(bsE[j], bsO[j]);

        #pragma unroll 1
        for (int p = p0; p < p1; p++) {
            const ulonglong2* R = (const ulonglong2*)(sRec + p * REC);
            ulonglong2 r0 = R[0], r1 = R[1], r2 = R[2], r3 = R[3];
            u64 nh2 = *(const u64*)(sRec + p * REC + 16);
            #pragma unroll
            for (int j = 0; j < QPT; j++) {
                u64 acc = fma2(q[j][0], r0.x, nh2);
                acc = fma2(q[j][1], r0.y, acc);
                acc = fma2(q[j][2], r1.x, acc);
                acc = fma2(q[j][3], r1.y, acc);
                acc = fma2(q[j][4], r2.x, acc);
                acc = fma2(q[j][5], r2.y, acc);
                acc = fma2(q[j][6], r3.x, acc);
                acc = fma2(q[j][7], r3.y, acc);
                float s0, s1; unpack2(acc, s0, s1);
                bsE[j] = fmaxf(bsE[j], s0);
                bsO[j] = fmaxf(bsO[j], s1);
            }
        }

        #pragma unroll
        for (int j = 0; j < QPT; j++)
            if (fmaxf(bsE[j], bsO[j]) > pb[j]) bc[j] = c;   // first chunk reaching max
    }

    // Resolve exact row inside winning chunk (bit-identical recompute), then atomicMax.
    #pragma unroll
    for (int j = 0; j < QPT; j++) {
        const float bs = fmaxf(bsE[j], bsO[j]);
        const int p0 = bc[j] * CH;
        const int p1 = min(p0 + CH, npairs);
        int row = 0;
        for (int p = p0; p < p1; p++) {
            const ulonglong2* R = (const ulonglong2*)(sRec + p * REC);
            ulonglong2 r0 = R[0], r1 = R[1], r2 = R[2], r3 = R[3];
            u64 nh2 = *(const u64*)(sRec + p * REC + 16);
            u64 acc = fma2(q[j][0], r0.x, nh2);
            acc = fma2(q[j][1], r0.y, acc);
            acc = fma2(q[j][2], r1.x, acc);
            acc = fma2(q[j][3], r1.y, acc);
            acc = fma2(q[j][4], r2.x, acc);
            acc = fma2(q[j][5], r2.y, acc);
            acc = fma2(q[j][6], r3.x, acc);
            acc = fma2(q[j][7], r3.y, acc);
            float s0, s1; unpack2(acc, s0, s1);
            if (s0 == bs) { row = 2 * p; break; }       // even row first (tie rule)
            if (s1 == bs) { row = 2 * p + 1; break; }
        }
        int qidx = qbase + t + TPB * j;
        u64 key = ((u64)enc_inc(bs) << 32) | (unsigned)(~(unsigned)(row + rowBase));
        atomicMax(&g_best[qidx], key);
    }

    // Last block of this query group finalizes (fused epilogue; non-blocking).
    __threadfence();
    if (t == 0) {
        unsigned c = atomicAdd(&g_cnt[grp], 1);
        sIsLast = (c == NSLICES - 1) ? 1u : 0u;
    }
    __syncthreads();
    if (!sIsLast) return;

    if (t < FDIM) sF[t] = fidx[t];
    __syncthreads();

    bool contig = ((sF[0] & 3) == 0);
    #pragma unroll
    for (int i = 1; i < FDIM; i++) contig = contig && (sF[i] == sF[0] + i);

    #pragma unroll
    for (int j = 0; j < QPT; j++) {
        int qidx = qbase + t + TPB * j;
        u64 v = *((volatile u64*)&g_best[qidx]);
        int row = (int)(~(unsigned)v);
        if (contig) {
            const float4* tr = (const float4*)(table + (size_t)row * NCOLS + sF[0]);
            const float4* fr = (const float4*)(feat + (size_t)qidx * FDIM);
            float4*       po = (float4*)(out + (size_t)qidx * FDIM);
            #pragma unroll
            for (int i = 0; i < FDIM / 4; i++) {
                float4 a = fr[i], b = tr[i];
                float4 o;
                o.x = a.x - b.x; o.y = a.y - b.y; o.z = a.z - b.z; o.w = a.w - b.w;
                po[i] = o;
            }
        } else {
            #pragma unroll
            for (int f = 0; f < FDIM; f++)
                out[(size_t)qidx * FDIM + f] =
                    feat[(size_t)qidx * FDIM + f] - table[(size_t)row * NCOLS + sF[f]];
        }
        g_best[qidx] = 0ULL;   // reset for next graph replay
    }
    __syncthreads();
    if (t == 0) g_cnt[grp] = 0;   // reset counter
}

extern "C" void kernel_launch(void* const* d_in, const int* in_sizes, int n_in,
                              void* d_out, int out_size) {
    const float* pk    = (const float*)d_in[0];  // predicted_key [1024,8]
    const float* feat  = (const float*)d_in[1];  // features      [1024,32]
    const float* table = (const float*)d_in[2];  // lookup_table  [100000,40]
    const int*   kidx  = (const int*)  d_in[3];  // lookup_key_indices [8]
    const int*   fidx  = (const int*)  d_in[4];  // feature_indices    [32]
    float* out = (float*)d_out;

    dim3 grid(NSLICES, QGROUPS);
    fused_kernel<<<grid, TPB>>>(pk, feat, table, kidx, fidx, out);
}

// round 11
// speedup vs baseline: 2.1303x; 2.1303x over previous
#include <cuda_runtime.h>
#include <cstdint>

// FeatureResidual: 1-NN over 8-dim keys in a 100000x40 table, then feature residual.
#define BATCH  1024
#define KDIM   8
#define FDIM   32
#define NROWS  100000
#define NCOLS  40

#define QGROUPS   2                 // query halves (512 queries each)
#define NSLICES   296               // grid = 296 x 2 = 592 blocks = 4/SM exact wave
#define TPB       128
#define QPT       4                 // queries per thread (128*4 = 512 per block)
#define ROWS_PER  338               // 296*338 >= 100000; last slice 290 (even)
#define MAXPAIRS  169
#define REC       20                // floats per pair record: 16 key + 2 nh + 2 pad

typedef unsigned long long u64;

// Per-query packed (enc(score) << 32 | ~row). Max = best score; ties -> lowest row.
// Zero-initialized at module load; finalize_kernel resets to 0 each launch.
__device__ u64 g_best[BATCH];

// ---------- f32x2 helpers ----------
__device__ __forceinline__ u64 pack2(float lo, float hi) {
    u64 r; asm("mov.b64 %0, {%1, %2};" : "=l"(r) : "f"(lo), "f"(hi)); return r;
}
__device__ __forceinline__ void unpack2(u64 p, float &lo, float &hi) {
    asm("mov.b64 {%0, %1}, %2;" : "=f"(lo), "=f"(hi) : "l"(p));
}
__device__ __forceinline__ u64 fma2(u64 a, u64 b, u64 c) {
    u64 d; asm("fma.rn.f32x2 %0, %1, %2, %3;" : "=l"(d) : "l"(a), "l"(b), "l"(c)); return d;
}
// Monotonic-increasing encode of float (u32 compare order == float order).
// Always > 0 for finite inputs, so g_best==0 is a safe atomicMax identity.
__device__ __forceinline__ unsigned enc_inc(float f) {
    int s = __float_as_int(f);
    return (s < 0) ? ~(unsigned)s : ((unsigned)s | 0x80000000u);
}

__global__ __launch_bounds__(TPB, 4)   // unfused: hot-loop liveness only, no epilogue
void argmin_kernel(const float* __restrict__ pk,
                   const float* __restrict__ table,
                   const int*   __restrict__ kidx) {
    // Pair record p (80B, 16B-aligned): [k0e,k0o, ..., k7e,k7o, nh_e,nh_o, pad,pad]
    __shared__ __align__(16) float sRec[MAXPAIRS * REC];
    __shared__ int sKidx[KDIM];

    const int t     = threadIdx.x;
    const int slice = blockIdx.x;
    const int grp   = blockIdx.y;

    if (t < KDIM) sKidx[t] = kidx[t];
    __syncthreads();

    const int rowBase = slice * ROWS_PER;
    const int nr      = min(ROWS_PER, NROWS - rowBase);   // even for this geometry
    const int npairs  = nr >> 1;

    // Stage keys interleaved by row pair (float2 fast path when key cols contiguous).
    bool kcontig = ((sKidx[0] & 1) == 0);
    #pragma unroll
    for (int i = 1; i < KDIM; i++) kcontig = kcontig && (sKidx[i] == sKidx[0] + i);
    if (kcontig) {
        const int c0 = sKidx[0];
        for (int e = t; e < nr * (KDIM / 2); e += TPB) {
            int r = e >> 2, c2 = e & 3;
            float2 v = *(const float2*)(table + (size_t)(rowBase + r) * NCOLS + c0 + 2 * c2);
            float* dst = sRec + (r >> 1) * REC + (r & 1);
            dst[4 * c2]     = v.x;
            dst[4 * c2 + 2] = v.y;
        }
    } else {
        for (int e = t; e < nr * KDIM; e += TPB) {
            int r = e >> 3, c = e & 7;
            float v = table[(size_t)(rowBase + r) * NCOLS + sKidx[c]];
            sRec[(r >> 1) * REC + (c << 1) + (r & 1)] = v;
        }
    }
    __syncthreads();
    // -0.5*||k||^2 per row, stored pair-adjacent at record offset 16.
    for (int r = t; r < nr; r += TPB) {
        const float* kr = sRec + (r >> 1) * REC + (r & 1);
        float s = kr[0] * kr[0];
        #pragma unroll
        for (int i = 1; i < KDIM; i++) s = fmaf(kr[2 * i], kr[2 * i], s);
        sRec[(r >> 1) * REC + 16 + (r & 1)] = -0.5f * s;
    }

    // Prologue: 4 queries per thread, duplicate-packed (64 regs).
    const int qbase = grp * (TPB * QPT);
    u64 q[QPT][KDIM];
    #pragma unroll
    for (int j = 0; j < QPT; j++) {
        const float4* pq = (const float4*)(pk + (size_t)(qbase + t + TPB * j) * KDIM);
        float4 a0 = pq[0], a1 = pq[1];
        float a[KDIM] = {a0.x, a0.y, a0.z, a0.w, a1.x, a1.y, a1.z, a1.w};
        #pragma unroll
        for (int i = 0; i < KDIM; i++) q[j][i] = pack2(a[i], a[i]);
    }

    float bs[QPT];
    int   bp[QPT];
    #pragma unroll
    for (int j = 0; j < QPT; j++) { bs[j] = -__int_as_float(0x7f800000); bp[j] = 0; }

    __syncthreads();

    // Flat hot loop: 4x LDS.128 + 1x LDS.64 hoisted per pair; per query
    // 8 FFMA2 + FMNMX + FSETP + 2 predicated moves. No chunking (spills), no pipeline.
    #pragma unroll 1
    for (int p = 0; p < npairs; p++) {
        const ulonglong2* R = (const ulonglong2*)(sRec + p * REC);
        ulonglong2 r0 = R[0], r1 = R[1], r2 = R[2], r3 = R[3];
        u64 nh2 = *(const u64*)(sRec + p * REC + 16);
        #pragma unroll
        for (int j = 0; j < QPT; j++) {
            // score = q.k - 0.5*||k||^2 for rows (2p, 2p+1) simultaneously
            u64 acc = fma2(q[j][0], r0.x, nh2);
            acc = fma2(q[j][1], r0.y, acc);
            acc = fma2(q[j][2], r1.x, acc);
            acc = fma2(q[j][3], r1.y, acc);
            acc = fma2(q[j][4], r2.x, acc);
            acc = fma2(q[j][5], r2.y, acc);
            acc = fma2(q[j][6], r3.x, acc);
            acc = fma2(q[j][7], r3.y, acc);
            float s0, s1; unpack2(acc, s0, s1);
            float m = fmaxf(s0, s1);
            if (m > bs[j]) { bs[j] = m; bp[j] = p; }   // strict: earliest pair wins ties
        }
    }

    // Resolve in-pair index for winning pair (bit-identical re-score), then atomicMax.
    #pragma unroll
    for (int j = 0; j < QPT; j++) {
        const ulonglong2* R = (const ulonglong2*)(sRec + bp[j] * REC);
        ulonglong2 r0 = R[0], r1 = R[1], r2 = R[2], r3 = R[3];
        u64 nh2 = *(const u64*)(sRec + bp[j] * REC + 16);
        u64 acc = fma2(q[j][0], r0.x, nh2);
        acc = fma2(q[j][1], r0.y, acc);
        acc = fma2(q[j][2], r1.x, acc);
        acc = fma2(q[j][3], r1.y, acc);
        acc = fma2(q[j][4], r2.x, acc);
        acc = fma2(q[j][5], r2.y, acc);
        acc = fma2(q[j][6], r3.x, acc);
        acc = fma2(q[j][7], r3.y, acc);
        float s0, s1; unpack2(acc, s0, s1);
        int row = rowBase + 2 * bp[j] + (s1 > s0 ? 1 : 0);  // even row wins in-pair ties
        int qidx = qbase + t + TPB * j;
        u64 key = ((u64)enc_inc(bs[j]) << 32) | (unsigned)(~(unsigned)row);
        atomicMax(&g_best[qidx], key);
    }
}

// One warp per query: lane0 reads winner, broadcasts, lanes compute residual,
// lane0 resets g_best for the next graph replay (deterministic).
__global__ void finalize_kernel(const float* __restrict__ feat,
                                const float* __restrict__ table,
                                const int*   __restrict__ fidx,
                                float* __restrict__ out) {
    int warp = (blockIdx.x * blockDim.x + threadIdx.x) >> 5;
    int lane = threadIdx.x & 31;
    if (warp >= BATCH) return;
    u64 v = 0;
    if (lane == 0) v = g_best[warp];
    v = __shfl_sync(0xFFFFFFFFu, v, 0);
    int row = (int)(~(unsigned)v);
    int col = fidx[lane];
    out[warp * FDIM + lane] = feat[warp * FDIM + lane]
                            - table[(size_t)row * NCOLS + col];
    if (lane == 0) g_best[warp] = 0ULL;
}

extern "C" void kernel_launch(void* const* d_in, const int* in_sizes, int n_in,
                              void* d_out, int out_size) {
    const float* pk    = (const float*)d_in[0];  // predicted_key [1024,8]
    const float* feat  = (const float*)d_in[1];  // features      [1024,32]
    const float* table = (const float*)d_in[2];  // lookup_table  [100000,40]
    const int*   kidx  = (const int*)  d_in[3];  // lookup_key_indices [8]
    const int*   fidx  = (const int*)  d_in[4];  // feature_indices    [32]
    float* out = (float*)d_out;

    dim3 grid(NSLICES, QGROUPS);
    argmin_kernel<<<grid, TPB>>>(pk, table, kidx);
    finalize_kernel<<<(BATCH * 32 + 255) / 256, 256>>>(feat, table, fidx, out);
}